// round 1
// baseline (speedup 1.0000x reference)
#include <cuda_runtime.h>
#include <math.h>

// Problem constants
#define BB    2
#define SS    2048
#define HH    4096
#define NHEAD 32
#define DD    128
#define MTOT  (BB*SS)   // 4096 rows for the projection GEMMs

// Scratch (no cudaMalloc allowed) — 132 MB total
__device__ float g_Q[(size_t)BB*SS*HH];     // 64 MB
__device__ float g_K[(size_t)BB*SS*DD];     // 2 MB
__device__ float g_V[(size_t)BB*SS*DD];     // 2 MB
__device__ float g_attn[(size_t)BB*SS*HH];  // 64 MB (scrambled layout)

// ---------------------------------------------------------------------------
// Generic C[M,N] = A[M,K] @ W[N,K]^T + bias[N]   (torch Linear semantics)
// 128x128 tile, BK=32, 256 threads, 8x8 per-thread microtile.
// Requires M%128==0, N%128==0, K%32==0 (true for all uses here).
// ---------------------------------------------------------------------------
__global__ void __launch_bounds__(256)
gemm_nt_bias(const float* __restrict__ A, const float* __restrict__ W,
             const float* __restrict__ bias, float* __restrict__ C,
             int M, int N, int Kdim)
{
    __shared__ float As[32][132];   // [k][m], padded
    __shared__ float Ws[32][132];   // [k][n], padded

    const int tid = threadIdx.x;
    const int m0  = blockIdx.y * 128;
    const int n0  = blockIdx.x * 128;
    const int tx  = tid & 15;
    const int ty  = tid >> 4;
    const int lk  = tid & 31;   // k within tile
    const int lr  = tid >> 5;   // row step base (0..7)

    float acc[8][8];
    #pragma unroll
    for (int i = 0; i < 8; i++)
        #pragma unroll
        for (int j = 0; j < 8; j++) acc[i][j] = 0.f;

    for (int k0 = 0; k0 < Kdim; k0 += 32) {
        #pragma unroll
        for (int s = 0; s < 16; s++)
            As[lk][s*8 + lr] = A[(size_t)(m0 + s*8 + lr)*Kdim + k0 + lk];
        #pragma unroll
        for (int s = 0; s < 16; s++)
            Ws[lk][s*8 + lr] = W[(size_t)(n0 + s*8 + lr)*Kdim + k0 + lk];
        __syncthreads();

        #pragma unroll
        for (int kk = 0; kk < 32; kk++) {
            float4 a0 = *(const float4*)&As[kk][ty*4];
            float4 a1 = *(const float4*)&As[kk][64 + ty*4];
            float4 b0 = *(const float4*)&Ws[kk][tx*4];
            float4 b1 = *(const float4*)&Ws[kk][64 + tx*4];
            float ar[8] = {a0.x,a0.y,a0.z,a0.w,a1.x,a1.y,a1.z,a1.w};
            float br[8] = {b0.x,b0.y,b0.z,b0.w,b1.x,b1.y,b1.z,b1.w};
            #pragma unroll
            for (int i = 0; i < 8; i++)
                #pragma unroll
                for (int j = 0; j < 8; j++)
                    acc[i][j] += ar[i]*br[j];
        }
        __syncthreads();
    }

    #pragma unroll
    for (int i = 0; i < 8; i++) {
        int row = m0 + ((i < 4) ? (ty*4 + i) : (64 + ty*4 + (i - 4)));
        #pragma unroll
        for (int jh = 0; jh < 2; jh++) {
            int col = n0 + ((jh == 0) ? (tx*4) : (64 + tx*4));
            float4 bv = *(const float4*)&bias[col];
            float4 v;
            v.x = acc[i][jh*4+0] + bv.x;
            v.y = acc[i][jh*4+1] + bv.y;
            v.z = acc[i][jh*4+2] + bv.z;
            v.w = acc[i][jh*4+3] + bv.w;
            *(float4*)&C[(size_t)row*N + col] = v;
        }
    }
}

// ---------------------------------------------------------------------------
// Fused MQA flash attention, fp32.
// grid: (q_tiles=32, heads=32, batch=2), 256 threads.
// BQ=64, BKV=64, D=128. Single shared K/V head per batch.
// Epilogue stores directly in the reference's scrambled layout:
//   A[b, (h*128+d)/2, (d&1)*2048 + s] = O[b,h,s,d]
// Dynamic smem: Qs/Ks/Vs 64x132 + Ps 64x68 = 118784 bytes.
// ---------------------------------------------------------------------------
#define ATTN_SMEM_FLOATS (8448*3 + 64*68)   // 29696 floats = 118784 B

__global__ void __launch_bounds__(256)
mqa_attn_kernel(const float* __restrict__ Q, const float* __restrict__ Kg,
                const float* __restrict__ Vg, float* __restrict__ Outp)
{
    extern __shared__ float sm[];
    float* Qs = sm;            // [64][132]
    float* Ks = sm + 8448;     // [64][132]  (reused as O staging at the end)
    float* Vs = sm + 16896;    // [64][132]
    float* Ps = sm + 25344;    // [64][68]

    const int tid = threadIdx.x;
    const int qt  = blockIdx.x;
    const int h   = blockIdx.y;
    const int b   = blockIdx.z;
    const int tx  = tid & 15;
    const int ty  = tid >> 4;

    const float scale = 0.08838834764831845f;   // 1/sqrt(128)
    const int q0 = qt * 64;

    // Load and pre-scale Q tile (64 x 128)
    const size_t qbase = ((size_t)b*SS + q0)*HH + (size_t)h*DD;
    for (int i = tid; i < 64*128; i += 256) {
        int r = i >> 7, d = i & 127;
        Qs[r*132 + d] = Q[qbase + (size_t)r*HH + d] * scale;
    }

    float m_i[4], l_i[4], acc_o[4][8];
    #pragma unroll
    for (int i = 0; i < 4; i++) {
        m_i[i] = -INFINITY; l_i[i] = 0.f;
        #pragma unroll
        for (int j = 0; j < 8; j++) acc_o[i][j] = 0.f;
    }

    const size_t kvbase0 = (size_t)b*SS*DD;

    for (int kt = 0; kt < SS/64; kt++) {
        __syncthreads();   // previous iteration's Ps/Vs reads complete
        const size_t kvb = kvbase0 + (size_t)kt*64*DD;
        for (int i = tid; i < 64*128; i += 256) {
            int r = i >> 7, d = i & 127;
            Ks[r*132 + d] = Kg[kvb + i];
            Vs[r*132 + d] = Vg[kvb + i];
        }
        __syncthreads();

        // S = Qs @ Ks^T  (64x64, K=128); thread owns rows ty*4+i, cols tx*4+j
        float sa[4][4];
        #pragma unroll
        for (int i = 0; i < 4; i++)
            #pragma unroll
            for (int j = 0; j < 4; j++) sa[i][j] = 0.f;

        #pragma unroll 8
        for (int d = 0; d < 128; d += 4) {
            float4 qv[4], kv[4];
            #pragma unroll
            for (int i = 0; i < 4; i++) qv[i] = *(const float4*)&Qs[(ty*4+i)*132 + d];
            #pragma unroll
            for (int j = 0; j < 4; j++) kv[j] = *(const float4*)&Ks[(tx*4+j)*132 + d];
            #pragma unroll
            for (int i = 0; i < 4; i++)
                #pragma unroll
                for (int j = 0; j < 4; j++)
                    sa[i][j] += qv[i].x*kv[j].x + qv[i].y*kv[j].y
                              + qv[i].z*kv[j].z + qv[i].w*kv[j].w;
        }

        // Online softmax; each row spans the 16 tx lanes (width-16 shuffles)
        #pragma unroll
        for (int i = 0; i < 4; i++) {
            float tmax = fmaxf(fmaxf(sa[i][0], sa[i][1]), fmaxf(sa[i][2], sa[i][3]));
            #pragma unroll
            for (int off = 8; off >= 1; off >>= 1)
                tmax = fmaxf(tmax, __shfl_xor_sync(0xffffffffu, tmax, off, 16));
            float mnew  = fmaxf(m_i[i], tmax);
            float alpha = __expf(m_i[i] - mnew);
            float rsum = 0.f;
            #pragma unroll
            for (int j = 0; j < 4; j++) { sa[i][j] = __expf(sa[i][j] - mnew); rsum += sa[i][j]; }
            #pragma unroll
            for (int off = 8; off >= 1; off >>= 1)
                rsum += __shfl_xor_sync(0xffffffffu, rsum, off, 16);
            l_i[i] = l_i[i]*alpha + rsum;
            m_i[i] = mnew;
            #pragma unroll
            for (int j = 0; j < 8; j++) acc_o[i][j] *= alpha;
            *(float4*)&Ps[(ty*4+i)*68 + tx*4] =
                make_float4(sa[i][0], sa[i][1], sa[i][2], sa[i][3]);
        }
        __syncthreads();

        // O += P @ V  (64x128, K=64); thread owns rows ty*4+i, d-cols tx*8..+7
        #pragma unroll 4
        for (int kv4 = 0; kv4 < 64; kv4 += 4) {
            float4 pv[4];
            #pragma unroll
            for (int i = 0; i < 4; i++) pv[i] = *(const float4*)&Ps[(ty*4+i)*68 + kv4];
            #pragma unroll
            for (int u = 0; u < 4; u++) {
                float4 v0 = *(const float4*)&Vs[(kv4+u)*132 + tx*8];
                float4 v1 = *(const float4*)&Vs[(kv4+u)*132 + tx*8 + 4];
                #pragma unroll
                for (int i = 0; i < 4; i++) {
                    float p = (u == 0) ? pv[i].x : (u == 1) ? pv[i].y
                            : (u == 2) ? pv[i].z : pv[i].w;
                    acc_o[i][0] += p*v0.x; acc_o[i][1] += p*v0.y;
                    acc_o[i][2] += p*v0.z; acc_o[i][3] += p*v0.w;
                    acc_o[i][4] += p*v1.x; acc_o[i][5] += p*v1.y;
                    acc_o[i][6] += p*v1.z; acc_o[i][7] += p*v1.w;
                }
            }
        }
    }

    // Normalize and stage O tile into smem (reuse Ks) for coalesced scrambled store
    __syncthreads();
    #pragma unroll
    for (int i = 0; i < 4; i++) {
        float inv = 1.f / l_i[i];
        #pragma unroll
        for (int j = 0; j < 8; j++) acc_o[i][j] *= inv;
        int r = ty*4 + i;
        *(float4*)&Ks[r*132 + tx*8]     = make_float4(acc_o[i][0], acc_o[i][1], acc_o[i][2], acc_o[i][3]);
        *(float4*)&Ks[r*132 + tx*8 + 4] = make_float4(acc_o[i][4], acc_o[i][5], acc_o[i][6], acc_o[i][7]);
    }
    __syncthreads();

    // Scrambled store: A[b, h*64 + d/2, (d&1)*2048 + q0 + s] = O[s][d]
    const size_t obase = (size_t)b*SS*HH;
    for (int i = tid; i < 64*128; i += 256) {
        int d = i >> 6;    // 0..127
        int s = i & 63;    // 0..63 (consecutive tid -> consecutive s: coalesced)
        size_t row = (size_t)h*64 + (d >> 1);
        size_t col = (size_t)(d & 1)*2048 + q0 + s;
        Outp[obase + row*HH + col] = Ks[s*132 + d];
    }
}

// ---------------------------------------------------------------------------
extern "C" void kernel_launch(void* const* d_in, const int* in_sizes, int n_in,
                              void* d_out, int out_size)
{
    const float* X  = (const float*)d_in[0];
    const float* Wq = (const float*)d_in[1];
    const float* bq = (const float*)d_in[2];
    const float* Wk = (const float*)d_in[3];
    const float* bk = (const float*)d_in[4];
    const float* Wv = (const float*)d_in[5];
    const float* bv = (const float*)d_in[6];
    const float* Wo = (const float*)d_in[7];
    const float* bo = (const float*)d_in[8];
    float* out = (float*)d_out;

    float *Qp, *Kp, *Vp, *Ap;
    cudaGetSymbolAddress((void**)&Qp, g_Q);
    cudaGetSymbolAddress((void**)&Kp, g_K);
    cudaGetSymbolAddress((void**)&Vp, g_V);
    cudaGetSymbolAddress((void**)&Ap, g_attn);

    // Opt-in dynamic smem for the attention kernel (deterministic, capture-safe)
    cudaFuncSetAttribute(mqa_attn_kernel,
                         cudaFuncAttributeMaxDynamicSharedMemorySize,
                         ATTN_SMEM_FLOATS * (int)sizeof(float));

    // 1) Projections
    gemm_nt_bias<<<dim3(HH/128, MTOT/128), 256>>>(X, Wq, bq, Qp, MTOT, HH, HH);
    gemm_nt_bias<<<dim3(DD/128, MTOT/128), 256>>>(X, Wk, bk, Kp, MTOT, DD, HH);
    gemm_nt_bias<<<dim3(DD/128, MTOT/128), 256>>>(X, Wv, bv, Vp, MTOT, DD, HH);

    // 2) Fused attention (writes scrambled layout)
    mqa_attn_kernel<<<dim3(SS/64, NHEAD, BB), 256,
                      ATTN_SMEM_FLOATS * sizeof(float)>>>(Qp, Kp, Vp, Ap);

    // 3) Output projection
    gemm_nt_bias<<<dim3(HH/128, MTOT/128), 256>>>(Ap, Wo, bo, out, MTOT, HH, HH);
}

// round 4
// speedup vs baseline: 1.4147x; 1.4147x over previous
#include <cuda_runtime.h>
#include <cstdint>
#include <math.h>

// Problem constants
#define BB    2
#define SS    2048
#define HH    4096
#define NHEAD 32
#define DD    128
#define MTOT  (BB*SS)

// Scratch (no cudaMalloc allowed)
__device__ float g_Q[(size_t)BB*SS*HH];     // 64 MB
__device__ float g_K[(size_t)BB*SS*DD];     // 2 MB
__device__ float g_V[(size_t)BB*SS*DD];     // 2 MB
__device__ float g_attn[(size_t)BB*SS*HH];  // 64 MB (scrambled layout)

// ===========================================================================
// tf32 mma.sync helper (sm_80+ path; legal on base sm_103 target)
// D(16x8) += A(16x8) @ B(8x8), A row-major, B col-major, fp32 accum.
// ===========================================================================
__device__ __forceinline__ void mma_tf32(float* d, const uint32_t* a, const uint32_t* b) {
    asm volatile(
        "mma.sync.aligned.m16n8k8.row.col.f32.tf32.tf32.f32 "
        "{%0,%1,%2,%3}, {%4,%5,%6,%7}, {%8,%9}, {%0,%1,%2,%3};"
        : "+f"(d[0]), "+f"(d[1]), "+f"(d[2]), "+f"(d[3])
        : "r"(a[0]), "r"(a[1]), "r"(a[2]), "r"(a[3]), "r"(b[0]), "r"(b[1]));
}

// Dekker-style split: a = hi + lo, hi = tf32-rounded(a), lo = tf32(a - hi)
__device__ __forceinline__ void split_tf32(float a, uint32_t& hi, uint32_t& lo) {
    uint32_t h;
    asm("cvt.rna.tf32.f32 %0, %1;" : "=r"(h) : "f"(a));
    float l = a - __uint_as_float(h);
    uint32_t l32;
    asm("cvt.rna.tf32.f32 %0, %1;" : "=r"(l32) : "f"(l));
    hi = h; lo = l32;
}

// ===========================================================================
// 3xTF32 tensor-core GEMM:  C[M,N] = A[M,K] @ W[N,K]^T + bias[N]
// CTA 128x128, K-chunk 32. 256 threads = 8 warps (2 x 4), warp tile 64x32.
// Fragment-permuted smem staging (validated in round 3):
//   A tiles (16x8): off = (tm*4+tk)*132 + lane*4 + reg   -> frag = lds.128
//   B tiles (8x8):  off = (tk*16+tn)*66 + lane*2 + reg   -> frag = lds.64
// Each fp32 product computed as hi*hi + lo*hi + hi*lo (3 MMAs) -> ~fp32 accuracy.
// Requires M%128==0, N%128==0, K%32==0.
// ===========================================================================
__global__ void __launch_bounds__(256, 2)
gemm_tf32_mma(const float* __restrict__ A, const float* __restrict__ W,
              const float* __restrict__ bias, float* __restrict__ C,
              int M, int N, int Kdim)
{
    __shared__ float sA[4224];   // 32 tiles * 132
    __shared__ float sB[4224];   // 64 tiles * 66

    const int tid = threadIdx.x;
    const int wid = tid >> 5;
    const int lane = tid & 31;
    const int wm = wid & 1;      // 0..1 (64-row group)
    const int wn = wid >> 1;     // 0..3 (32-col group)
    const int m0 = blockIdx.y * 128;
    const int n0 = blockIdx.x * 128;

    float acc[4][4][4];
    #pragma unroll
    for (int i = 0; i < 4; i++)
        #pragma unroll
        for (int j = 0; j < 4; j++)
            #pragma unroll
            for (int r = 0; r < 4; r++) acc[i][j][r] = 0.f;

    const int nch = Kdim >> 5;

    for (int c = 0; c < nch; c++) {
        __syncthreads();   // previous compute finished reading smem
        const int k0 = c << 5;
        // gmem -> smem (fragment-permuted), no cross-iter prefetch (occ=2 hides)
        #pragma unroll
        for (int t = 0; t < 4; t++) {
            int id = tid + (t << 8);
            int kg = id & 7, r = id >> 3;
            float4 va = *(const float4*)(A + (size_t)(m0 + r) * Kdim + k0 + kg * 4);
            float4 vb = *(const float4*)(W + (size_t)(n0 + r) * Kdim + k0 + kg * 4);
            {   // A
                int tm = r >> 4, rr = r & 15, tk = kg >> 1;
                int reg = ((kg & 1) << 1) + (rr >> 3);
                float* dst = sA + (tm * 4 + tk) * 132 + (rr & 7) * 16 + reg;
                dst[0] = va.x; dst[4] = va.y; dst[8] = va.z; dst[12] = va.w;
            }
            {   // B
                int tn = r >> 3, nn = r & 7, tk = kg >> 1;
                int reg = kg & 1;
                float* dst = sB + (tk * 16 + tn) * 66 + nn * 8 + reg;
                dst[0] = vb.x; dst[2] = vb.y; dst[4] = vb.z; dst[6] = vb.w;
            }
        }
        __syncthreads();

        // compute: 4 ksteps x (4 mtiles x 4 ntiles) x 3 split-MMAs
        #pragma unroll
        for (int ks = 0; ks < 4; ks++) {
            uint32_t ah[4][4], al[4][4];
            #pragma unroll
            for (int mt = 0; mt < 4; mt++) {
                float4 v = *(const float4*)&sA[((wm * 4 + mt) * 4 + ks) * 132 + lane * 4];
                split_tf32(v.x, ah[mt][0], al[mt][0]);
                split_tf32(v.y, ah[mt][1], al[mt][1]);
                split_tf32(v.z, ah[mt][2], al[mt][2]);
                split_tf32(v.w, ah[mt][3], al[mt][3]);
            }
            uint32_t bh[4][2], bl[4][2];
            #pragma unroll
            for (int tn = 0; tn < 4; tn++) {
                float2 v = *(const float2*)&sB[(ks * 16 + wn * 4 + tn) * 66 + lane * 2];
                split_tf32(v.x, bh[tn][0], bl[tn][0]);
                split_tf32(v.y, bh[tn][1], bl[tn][1]);
            }
            #pragma unroll
            for (int mt = 0; mt < 4; mt++)
                #pragma unroll
                for (int tn = 0; tn < 4; tn++) {
                    mma_tf32(acc[mt][tn], al[mt], bh[tn]);
                    mma_tf32(acc[mt][tn], ah[mt], bl[tn]);
                    mma_tf32(acc[mt][tn], ah[mt], bh[tn]);
                }
        }
    }

    // Epilogue: C = acc + bias
    #pragma unroll
    for (int mt = 0; mt < 4; mt++) {
        int row = m0 + wm * 64 + mt * 16 + (lane >> 2);
        #pragma unroll
        for (int tn = 0; tn < 4; tn++) {
            int col = n0 + wn * 32 + tn * 8 + (lane & 3) * 2;
            float2 bv = *(const float2*)(bias + col);
            float2 v0, v1;
            v0.x = acc[mt][tn][0] + bv.x; v0.y = acc[mt][tn][1] + bv.y;
            v1.x = acc[mt][tn][2] + bv.x; v1.y = acc[mt][tn][3] + bv.y;
            *(float2*)(C + (size_t)row * N + col) = v0;
            *(float2*)(C + (size_t)(row + 8) * N + col) = v1;
        }
    }
}

// ---------------------------------------------------------------------------
// Fused MQA flash attention, fp32. BQ=64, BKV=32 (smem 76.8KB -> 2 CTAs/SM).
// Epilogue stores scrambled layout: A[b, h*64 + d/2, (d&1)*2048 + q0 + s]
// ---------------------------------------------------------------------------
#define ATTN_SMEM_FLOATS (8448 + 4224 + 4224 + 64*36)   // 19200 floats = 76800 B

__global__ void __launch_bounds__(256, 2)
mqa_attn_kernel(const float* __restrict__ Q, const float* __restrict__ Kg,
                const float* __restrict__ Vg, float* __restrict__ Outp)
{
    extern __shared__ float sm[];
    float* Qs = sm;             // [64][132]
    float* Ks = sm + 8448;      // [32][132]
    float* Vs = sm + 12672;     // [32][132]
    float* Ps = sm + 16896;     // [64][36]

    const int tid = threadIdx.x;
    const int qt  = blockIdx.x;
    const int h   = blockIdx.y;
    const int b   = blockIdx.z;
    const int tx  = tid & 15;
    const int ty  = tid >> 4;

    const float scale = 0.08838834764831845f;
    const int q0 = qt * 64;

    const size_t qbase = ((size_t)b*SS + q0)*HH + (size_t)h*DD;
    for (int i = tid; i < 64*128; i += 256) {
        int r = i >> 7, d = i & 127;
        Qs[r*132 + d] = Q[qbase + (size_t)r*HH + d] * scale;
    }

    float m_i[4], l_i[4], acc_o[4][8];
    #pragma unroll
    for (int i = 0; i < 4; i++) {
        m_i[i] = -INFINITY; l_i[i] = 0.f;
        #pragma unroll
        for (int j = 0; j < 8; j++) acc_o[i][j] = 0.f;
    }

    const size_t kvbase0 = (size_t)b*SS*DD;

    for (int kt = 0; kt < SS/32; kt++) {
        __syncthreads();
        const size_t kvb = kvbase0 + (size_t)kt*32*DD;
        for (int i = tid; i < 32*128; i += 256) {
            int r = i >> 7, d = i & 127;
            Ks[r*132 + d] = Kg[kvb + i];
            Vs[r*132 + d] = Vg[kvb + i];
        }
        __syncthreads();

        // S = Qs @ Ks^T  (64x32, K=128); thread: rows ty*4+i, cols tx*2+j
        float sa[4][2];
        #pragma unroll
        for (int i = 0; i < 4; i++) { sa[i][0] = 0.f; sa[i][1] = 0.f; }

        #pragma unroll 8
        for (int d = 0; d < 128; d += 4) {
            float4 qv[4], kv[2];
            #pragma unroll
            for (int i = 0; i < 4; i++) qv[i] = *(const float4*)&Qs[(ty*4+i)*132 + d];
            #pragma unroll
            for (int j = 0; j < 2; j++) kv[j] = *(const float4*)&Ks[(tx*2+j)*132 + d];
            #pragma unroll
            for (int i = 0; i < 4; i++)
                #pragma unroll
                for (int j = 0; j < 2; j++)
                    sa[i][j] += qv[i].x*kv[j].x + qv[i].y*kv[j].y
                              + qv[i].z*kv[j].z + qv[i].w*kv[j].w;
        }

        // Online softmax over the 32 kv cols (16 tx lanes x 2 each)
        #pragma unroll
        for (int i = 0; i < 4; i++) {
            float tmax = fmaxf(sa[i][0], sa[i][1]);
            #pragma unroll
            for (int off = 8; off >= 1; off >>= 1)
                tmax = fmaxf(tmax, __shfl_xor_sync(0xffffffffu, tmax, off, 16));
            float mnew  = fmaxf(m_i[i], tmax);
            float alpha = __expf(m_i[i] - mnew);
            float rsum;
            sa[i][0] = __expf(sa[i][0] - mnew);
            sa[i][1] = __expf(sa[i][1] - mnew);
            rsum = sa[i][0] + sa[i][1];
            #pragma unroll
            for (int off = 8; off >= 1; off >>= 1)
                rsum += __shfl_xor_sync(0xffffffffu, rsum, off, 16);
            l_i[i] = l_i[i]*alpha + rsum;
            m_i[i] = mnew;
            #pragma unroll
            for (int j = 0; j < 8; j++) acc_o[i][j] *= alpha;
            *(float2*)&Ps[(ty*4+i)*36 + tx*2] = make_float2(sa[i][0], sa[i][1]);
        }
        __syncthreads();

        // O += P @ V  (64x128, K=32); thread: rows ty*4+i, d-cols tx*8..+7
        #pragma unroll 2
        for (int kv4 = 0; kv4 < 32; kv4 += 4) {
            float4 pv[4];
            #pragma unroll
            for (int i = 0; i < 4; i++) pv[i] = *(const float4*)&Ps[(ty*4+i)*36 + kv4];
            #pragma unroll
            for (int u = 0; u < 4; u++) {
                float4 v0 = *(const float4*)&Vs[(kv4+u)*132 + tx*8];
                float4 v1 = *(const float4*)&Vs[(kv4+u)*132 + tx*8 + 4];
                #pragma unroll
                for (int i = 0; i < 4; i++) {
                    float p = (u == 0) ? pv[i].x : (u == 1) ? pv[i].y
                            : (u == 2) ? pv[i].z : pv[i].w;
                    acc_o[i][0] += p*v0.x; acc_o[i][1] += p*v0.y;
                    acc_o[i][2] += p*v0.z; acc_o[i][3] += p*v0.w;
                    acc_o[i][4] += p*v1.x; acc_o[i][5] += p*v1.y;
                    acc_o[i][6] += p*v1.z; acc_o[i][7] += p*v1.w;
                }
            }
        }
    }

    // Normalize, stage O tile into Qs (free now), then scrambled store
    __syncthreads();
    #pragma unroll
    for (int i = 0; i < 4; i++) {
        float inv = 1.f / l_i[i];
        #pragma unroll
        for (int j = 0; j < 8; j++) acc_o[i][j] *= inv;
        int r = ty*4 + i;
        *(float4*)&Qs[r*132 + tx*8]     = make_float4(acc_o[i][0], acc_o[i][1], acc_o[i][2], acc_o[i][3]);
        *(float4*)&Qs[r*132 + tx*8 + 4] = make_float4(acc_o[i][4], acc_o[i][5], acc_o[i][6], acc_o[i][7]);
    }
    __syncthreads();

    const size_t obase = (size_t)b*SS*HH;
    for (int i = tid; i < 64*128; i += 256) {
        int d = i >> 6;
        int s = i & 63;
        size_t row = (size_t)h*64 + (d >> 1);
        size_t col = (size_t)(d & 1)*2048 + q0 + s;
        Outp[obase + row*HH + col] = Qs[s*132 + d];
    }
}

// ---------------------------------------------------------------------------
extern "C" void kernel_launch(void* const* d_in, const int* in_sizes, int n_in,
                              void* d_out, int out_size)
{
    const float* X  = (const float*)d_in[0];
    const float* Wq = (const float*)d_in[1];
    const float* bq = (const float*)d_in[2];
    const float* Wk = (const float*)d_in[3];
    const float* bk = (const float*)d_in[4];
    const float* Wv = (const float*)d_in[5];
    const float* bv = (const float*)d_in[6];
    const float* Wo = (const float*)d_in[7];
    const float* bo = (const float*)d_in[8];
    float* out = (float*)d_out;

    float *Qp, *Kp, *Vp, *Ap;
    cudaGetSymbolAddress((void**)&Qp, g_Q);
    cudaGetSymbolAddress((void**)&Kp, g_K);
    cudaGetSymbolAddress((void**)&Vp, g_V);
    cudaGetSymbolAddress((void**)&Ap, g_attn);

    cudaFuncSetAttribute(mqa_attn_kernel,
                         cudaFuncAttributeMaxDynamicSharedMemorySize,
                         ATTN_SMEM_FLOATS * (int)sizeof(float));

    // 1) Projections (3xTF32 mma.sync tensor cores)
    gemm_tf32_mma<<<dim3(HH/128, MTOT/128), 256>>>(X, Wq, bq, Qp, MTOT, HH, HH);
    gemm_tf32_mma<<<dim3(DD/128, MTOT/128), 256>>>(X, Wk, bk, Kp, MTOT, DD, HH);
    gemm_tf32_mma<<<dim3(DD/128, MTOT/128), 256>>>(X, Wv, bv, Vp, MTOT, DD, HH);

    // 2) Fused attention (fp32, BKV=32, 2 CTAs/SM)
    mqa_attn_kernel<<<dim3(SS/64, NHEAD, BB), 256,
                      ATTN_SMEM_FLOATS * sizeof(float)>>>(Qp, Kp, Vp, Ap);

    // 3) Output projection (3xTF32 mma.sync)
    gemm_tf32_mma<<<dim3(HH/128, MTOT/128), 256>>>(Ap, Wo, bo, out, MTOT, HH, HH);
}

// round 5
// speedup vs baseline: 1.5470x; 1.0935x over previous
#include <cuda_runtime.h>
#include <cstdint>
#include <math.h>

// Problem constants
#define BB    2
#define SS    2048
#define HH    4096
#define NHEAD 32
#define DD    128
#define MTOT  (BB*SS)

// Scratch (no cudaMalloc allowed)
__device__ float g_Q[(size_t)BB*SS*HH];     // 64 MB
__device__ float g_K[(size_t)BB*SS*DD];     // 2 MB
__device__ float g_V[(size_t)BB*SS*DD];     // 2 MB
__device__ float g_attn[(size_t)BB*SS*HH];  // 64 MB (scrambled layout)
__device__ float g_part[(size_t)4*MTOT*DD]; // 8 MB split-K partials

// ===========================================================================
// Helpers
// ===========================================================================
__device__ __forceinline__ uint32_t smem_u32(const void* p) {
    uint32_t a;
    asm("{ .reg .u64 t; cvta.to.shared.u64 t, %1; cvt.u32.u64 %0, t; }" : "=r"(a) : "l"(p));
    return a;
}
__device__ __forceinline__ void cp_async16(uint32_t dst, const void* src) {
    asm volatile("cp.async.cg.shared.global [%0], [%1], 16;" :: "r"(dst), "l"(src));
}

// tf32 mma.sync: D(16x8) += A(16x8) @ B(8x8), row.col, fp32 accum
__device__ __forceinline__ void mma_tf32(float* d, const uint32_t* a, const uint32_t* b) {
    asm volatile(
        "mma.sync.aligned.m16n8k8.row.col.f32.tf32.tf32.f32 "
        "{%0,%1,%2,%3}, {%4,%5,%6,%7}, {%8,%9}, {%0,%1,%2,%3};"
        : "+f"(d[0]), "+f"(d[1]), "+f"(d[2]), "+f"(d[3])
        : "r"(a[0]), "r"(a[1]), "r"(a[2]), "r"(a[3]), "r"(b[0]), "r"(b[1]));
}

// Dekker split: a = hi + lo (both tf32-representable)
__device__ __forceinline__ void split_tf32(float a, uint32_t& hi, uint32_t& lo) {
    uint32_t h;
    asm("cvt.rna.tf32.f32 %0, %1;" : "=r"(h) : "f"(a));
    float l = a - __uint_as_float(h);
    uint32_t l32;
    asm("cvt.rna.tf32.f32 %0, %1;" : "=r"(l32) : "f"(l));
    hi = h; lo = l32;
}

// ===========================================================================
// 3xTF32 tensor-core GEMM with cp.async double-buffered pipeline.
//   C[M,N] = A[M,K] @ W[N,K]^T (+ bias[N] when gridDim.z == 1)
// CTA 128x128, K-chunk 32, 2-stage smem pipeline, 8 warps (2x4), warp 64x32.
// Smem: raw row-major tiles [128][36] (stride 36 -> cp.async 16B-aligned rows,
// and fragment lds.32 pattern (4g+t)%32 is bank-conflict-free).
// Split-K: blockIdx.z selects K segment of length kLen; partials (no bias)
// are written to C + z*M*N when gridDim.z > 1.
// ===========================================================================
#define GSTRIDE 36
#define GBUF    (128*GSTRIDE)          // 4608 floats per tile buffer
#define GEMM_SMEM_BYTES (4*GBUF*4)     // 2 stages x (A+B) = 73728 B

__global__ void __launch_bounds__(256, 2)
gemm_tf32_mma(const float* __restrict__ A, const float* __restrict__ W,
              const float* __restrict__ bias, float* __restrict__ C,
              int M, int N, int Kdim, int kLen)
{
    extern __shared__ float smem[];
    float* sA = smem;              // [2][GBUF]
    float* sB = smem + 2*GBUF;     // [2][GBUF]
    const uint32_t sAu = smem_u32(sA);
    const uint32_t sBu = smem_u32(sB);

    const int tid = threadIdx.x;
    const int wid = tid >> 5;
    const int lane = tid & 31;
    const int g = lane >> 2;       // 0..7
    const int t = lane & 3;        // 0..3
    const int wm = wid & 1;
    const int wn = wid >> 1;
    const int m0 = blockIdx.y * 128;
    const int n0 = blockIdx.x * 128;
    const int kOff = blockIdx.z * kLen;

    float acc[4][4][4];
    #pragma unroll
    for (int i = 0; i < 4; i++)
        #pragma unroll
        for (int j = 0; j < 4; j++)
            #pragma unroll
            for (int r = 0; r < 4; r++) acc[i][j][r] = 0.f;

    const int nch = kLen >> 5;

    // copy indices: id = tid + 256*tt -> row = id>>3 (0..127), kg = id&7
    const int crow = tid >> 3;     // base row for tt=0 (0..31)
    const int ckg  = tid & 7;

    // ---- prologue: stage chunk 0 into buffer 0
    {
        const int k0 = kOff;
        #pragma unroll
        for (int tt = 0; tt < 4; tt++) {
            int r = crow + tt * 32;
            uint32_t doff = (uint32_t)(r * GSTRIDE + ckg * 4) * 4u;
            cp_async16(sAu + doff, A + (size_t)(m0 + r) * Kdim + k0 + ckg * 4);
            cp_async16(sBu + doff, W + (size_t)(n0 + r) * Kdim + k0 + ckg * 4);
        }
        asm volatile("cp.async.commit_group;" ::: "memory");
    }

    for (int c = 0; c < nch; c++) {
        const int buf = c & 1;
        if (c + 1 < nch) {
            const int k0 = kOff + ((c + 1) << 5);
            const uint32_t nb = (uint32_t)((c + 1) & 1) * (GBUF * 4u);
            #pragma unroll
            for (int tt = 0; tt < 4; tt++) {
                int r = crow + tt * 32;
                uint32_t doff = nb + (uint32_t)(r * GSTRIDE + ckg * 4) * 4u;
                cp_async16(sAu + doff, A + (size_t)(m0 + r) * Kdim + k0 + ckg * 4);
                cp_async16(sBu + doff, W + (size_t)(n0 + r) * Kdim + k0 + ckg * 4);
            }
            asm volatile("cp.async.commit_group;" ::: "memory");
            asm volatile("cp.async.wait_group 1;" ::: "memory");
        } else {
            asm volatile("cp.async.wait_group 0;" ::: "memory");
        }
        __syncthreads();

        const float* a_s = sA + buf * GBUF;
        const float* b_s = sB + buf * GBUF;

        #pragma unroll
        for (int ks = 0; ks < 4; ks++) {
            const int kb = ks * 8;
            uint32_t ah[4][4], al[4][4];
            #pragma unroll
            for (int mt = 0; mt < 4; mt++) {
                const int rb = (wm * 64 + mt * 16 + g) * GSTRIDE + kb + t;
                split_tf32(a_s[rb],                 ah[mt][0], al[mt][0]);
                split_tf32(a_s[rb + 8*GSTRIDE],     ah[mt][1], al[mt][1]);
                split_tf32(a_s[rb + 4],             ah[mt][2], al[mt][2]);
                split_tf32(a_s[rb + 8*GSTRIDE + 4], ah[mt][3], al[mt][3]);
            }
            uint32_t bh[4][2], bl[4][2];
            #pragma unroll
            for (int tn = 0; tn < 4; tn++) {
                const int nb2 = (wn * 32 + tn * 8 + g) * GSTRIDE + kb + t;
                split_tf32(b_s[nb2],     bh[tn][0], bl[tn][0]);
                split_tf32(b_s[nb2 + 4], bh[tn][1], bl[tn][1]);
            }
            #pragma unroll
            for (int mt = 0; mt < 4; mt++)
                #pragma unroll
                for (int tn = 0; tn < 4; tn++) {
                    mma_tf32(acc[mt][tn], al[mt], bh[tn]);
                    mma_tf32(acc[mt][tn], ah[mt], bl[tn]);
                    mma_tf32(acc[mt][tn], ah[mt], bh[tn]);
                }
        }
        __syncthreads();
    }

    // Epilogue
    const bool full = (gridDim.z == 1);
    float* Cout = C + (full ? (size_t)0 : (size_t)blockIdx.z * M * N);
    #pragma unroll
    for (int mt = 0; mt < 4; mt++) {
        int row = m0 + wm * 64 + mt * 16 + g;
        #pragma unroll
        for (int tn = 0; tn < 4; tn++) {
            int col = n0 + wn * 32 + tn * 8 + t * 2;
            float bx = 0.f, by = 0.f;
            if (full) { float2 bv = *(const float2*)(bias + col); bx = bv.x; by = bv.y; }
            float2 v0, v1;
            v0.x = acc[mt][tn][0] + bx; v0.y = acc[mt][tn][1] + by;
            v1.x = acc[mt][tn][2] + bx; v1.y = acc[mt][tn][3] + by;
            *(float2*)(Cout + (size_t)row * N + col) = v0;
            *(float2*)(Cout + (size_t)(row + 8) * N + col) = v1;
        }
    }
}

// Deterministic split-K reduce: out[i] = sum_{s<4} part[s][i] + bias[i % N]
__global__ void __launch_bounds__(256)
reduce4_bias(const float* __restrict__ part, const float* __restrict__ bias,
             float* __restrict__ out, int MN, int N)
{
    int i = blockIdx.x * 256 + threadIdx.x;
    if (i < MN) {
        float v = (part[i] + part[(size_t)MN + i])
                + (part[(size_t)2*MN + i] + part[(size_t)3*MN + i]);
        out[i] = v + bias[i & (N - 1)];
    }
}

// ---------------------------------------------------------------------------
// Fused MQA flash attention, fp32. BQ=64, BKV=32, 2 CTAs/SM. (validated R4)
// Epilogue stores scrambled layout: A[b, h*64 + d/2, (d&1)*2048 + q0 + s]
// ---------------------------------------------------------------------------
#define ATTN_SMEM_FLOATS (8448 + 4224 + 4224 + 64*36)   // 76800 B

__global__ void __launch_bounds__(256, 2)
mqa_attn_kernel(const float* __restrict__ Q, const float* __restrict__ Kg,
                const float* __restrict__ Vg, float* __restrict__ Outp)
{
    extern __shared__ float sm[];
    float* Qs = sm;             // [64][132]
    float* Ks = sm + 8448;      // [32][132]
    float* Vs = sm + 12672;     // [32][132]
    float* Ps = sm + 16896;     // [64][36]

    const int tid = threadIdx.x;
    const int qt  = blockIdx.x;
    const int h   = blockIdx.y;
    const int b   = blockIdx.z;
    const int tx  = tid & 15;
    const int ty  = tid >> 4;

    const float scale = 0.08838834764831845f;
    const int q0 = qt * 64;

    const size_t qbase = ((size_t)b*SS + q0)*HH + (size_t)h*DD;
    for (int i = tid; i < 64*128; i += 256) {
        int r = i >> 7, d = i & 127;
        Qs[r*132 + d] = Q[qbase + (size_t)r*HH + d] * scale;
    }

    float m_i[4], l_i[4], acc_o[4][8];
    #pragma unroll
    for (int i = 0; i < 4; i++) {
        m_i[i] = -INFINITY; l_i[i] = 0.f;
        #pragma unroll
        for (int j = 0; j < 8; j++) acc_o[i][j] = 0.f;
    }

    const size_t kvbase0 = (size_t)b*SS*DD;

    for (int kt = 0; kt < SS/32; kt++) {
        __syncthreads();
        const size_t kvb = kvbase0 + (size_t)kt*32*DD;
        for (int i = tid; i < 32*128; i += 256) {
            int r = i >> 7, d = i & 127;
            Ks[r*132 + d] = Kg[kvb + i];
            Vs[r*132 + d] = Vg[kvb + i];
        }
        __syncthreads();

        float sa[4][2];
        #pragma unroll
        for (int i = 0; i < 4; i++) { sa[i][0] = 0.f; sa[i][1] = 0.f; }

        #pragma unroll 8
        for (int d = 0; d < 128; d += 4) {
            float4 qv[4], kv[2];
            #pragma unroll
            for (int i = 0; i < 4; i++) qv[i] = *(const float4*)&Qs[(ty*4+i)*132 + d];
            #pragma unroll
            for (int j = 0; j < 2; j++) kv[j] = *(const float4*)&Ks[(tx*2+j)*132 + d];
            #pragma unroll
            for (int i = 0; i < 4; i++)
                #pragma unroll
                for (int j = 0; j < 2; j++)
                    sa[i][j] += qv[i].x*kv[j].x + qv[i].y*kv[j].y
                              + qv[i].z*kv[j].z + qv[i].w*kv[j].w;
        }

        #pragma unroll
        for (int i = 0; i < 4; i++) {
            float tmax = fmaxf(sa[i][0], sa[i][1]);
            #pragma unroll
            for (int off = 8; off >= 1; off >>= 1)
                tmax = fmaxf(tmax, __shfl_xor_sync(0xffffffffu, tmax, off, 16));
            float mnew  = fmaxf(m_i[i], tmax);
            float alpha = __expf(m_i[i] - mnew);
            float rsum;
            sa[i][0] = __expf(sa[i][0] - mnew);
            sa[i][1] = __expf(sa[i][1] - mnew);
            rsum = sa[i][0] + sa[i][1];
            #pragma unroll
            for (int off = 8; off >= 1; off >>= 1)
                rsum += __shfl_xor_sync(0xffffffffu, rsum, off, 16);
            l_i[i] = l_i[i]*alpha + rsum;
            m_i[i] = mnew;
            #pragma unroll
            for (int j = 0; j < 8; j++) acc_o[i][j] *= alpha;
            *(float2*)&Ps[(ty*4+i)*36 + tx*2] = make_float2(sa[i][0], sa[i][1]);
        }
        __syncthreads();

        #pragma unroll 2
        for (int kv4 = 0; kv4 < 32; kv4 += 4) {
            float4 pv[4];
            #pragma unroll
            for (int i = 0; i < 4; i++) pv[i] = *(const float4*)&Ps[(ty*4+i)*36 + kv4];
            #pragma unroll
            for (int u = 0; u < 4; u++) {
                float4 v0 = *(const float4*)&Vs[(kv4+u)*132 + tx*8];
                float4 v1 = *(const float4*)&Vs[(kv4+u)*132 + tx*8 + 4];
                #pragma unroll
                for (int i = 0; i < 4; i++) {
                    float p = (u == 0) ? pv[i].x : (u == 1) ? pv[i].y
                            : (u == 2) ? pv[i].z : pv[i].w;
                    acc_o[i][0] += p*v0.x; acc_o[i][1] += p*v0.y;
                    acc_o[i][2] += p*v0.z; acc_o[i][3] += p*v0.w;
                    acc_o[i][4] += p*v1.x; acc_o[i][5] += p*v1.y;
                    acc_o[i][6] += p*v1.z; acc_o[i][7] += p*v1.w;
                }
            }
        }
    }

    __syncthreads();
    #pragma unroll
    for (int i = 0; i < 4; i++) {
        float inv = 1.f / l_i[i];
        #pragma unroll
        for (int j = 0; j < 8; j++) acc_o[i][j] *= inv;
        int r = ty*4 + i;
        *(float4*)&Qs[r*132 + tx*8]     = make_float4(acc_o[i][0], acc_o[i][1], acc_o[i][2], acc_o[i][3]);
        *(float4*)&Qs[r*132 + tx*8 + 4] = make_float4(acc_o[i][4], acc_o[i][5], acc_o[i][6], acc_o[i][7]);
    }
    __syncthreads();

    const size_t obase = (size_t)b*SS*HH;
    for (int i = tid; i < 64*128; i += 256) {
        int d = i >> 6;
        int s = i & 63;
        size_t row = (size_t)h*64 + (d >> 1);
        size_t col = (size_t)(d & 1)*2048 + q0 + s;
        Outp[obase + row*HH + col] = Qs[s*132 + d];
    }
}

// ---------------------------------------------------------------------------
extern "C" void kernel_launch(void* const* d_in, const int* in_sizes, int n_in,
                              void* d_out, int out_size)
{
    const float* X  = (const float*)d_in[0];
    const float* Wq = (const float*)d_in[1];
    const float* bq = (const float*)d_in[2];
    const float* Wk = (const float*)d_in[3];
    const float* bk = (const float*)d_in[4];
    const float* Wv = (const float*)d_in[5];
    const float* bv = (const float*)d_in[6];
    const float* Wo = (const float*)d_in[7];
    const float* bo = (const float*)d_in[8];
    float* out = (float*)d_out;

    float *Qp, *Kp, *Vp, *Ap, *Pp;
    cudaGetSymbolAddress((void**)&Qp, g_Q);
    cudaGetSymbolAddress((void**)&Kp, g_K);
    cudaGetSymbolAddress((void**)&Vp, g_V);
    cudaGetSymbolAddress((void**)&Ap, g_attn);
    cudaGetSymbolAddress((void**)&Pp, g_part);

    cudaFuncSetAttribute(gemm_tf32_mma,
                         cudaFuncAttributeMaxDynamicSharedMemorySize, GEMM_SMEM_BYTES);
    cudaFuncSetAttribute(mqa_attn_kernel,
                         cudaFuncAttributeMaxDynamicSharedMemorySize,
                         ATTN_SMEM_FLOATS * (int)sizeof(float));

    // 1) Q projection (full K)
    gemm_tf32_mma<<<dim3(HH/128, MTOT/128, 1), 256, GEMM_SMEM_BYTES>>>(
        X, Wq, bq, Qp, MTOT, HH, HH, HH);

    // 2) K projection (split-K=4 -> partials -> reduce+bias)
    gemm_tf32_mma<<<dim3(DD/128, MTOT/128, 4), 256, GEMM_SMEM_BYTES>>>(
        X, Wk, nullptr, Pp, MTOT, DD, HH, HH/4);
    reduce4_bias<<<(MTOT*DD + 255)/256, 256>>>(Pp, bk, Kp, MTOT*DD, DD);

    // 3) V projection (split-K=4)
    gemm_tf32_mma<<<dim3(DD/128, MTOT/128, 4), 256, GEMM_SMEM_BYTES>>>(
        X, Wv, nullptr, Pp, MTOT, DD, HH, HH/4);
    reduce4_bias<<<(MTOT*DD + 255)/256, 256>>>(Pp, bv, Vp, MTOT*DD, DD);

    // 4) Fused attention (fp32, BKV=32, 2 CTAs/SM)
    mqa_attn_kernel<<<dim3(SS/64, NHEAD, BB), 256,
                      ATTN_SMEM_FLOATS * sizeof(float)>>>(Qp, Kp, Vp, Ap);

    // 5) Output projection (full K)
    gemm_tf32_mma<<<dim3(HH/128, MTOT/128, 1), 256, GEMM_SMEM_BYTES>>>(
        Ap, Wo, bo, out, MTOT, HH, HH, HH);
}